// round 1
// baseline (speedup 1.0000x reference)
#include <cuda_runtime.h>

#define NN 100000
#define NE 1600000
#define NG 64
#define D  64
#define SCAN_B 1024
#define NB_SCAN ((NN + SCAN_B - 1) / SCAN_B)   // 98

// ---------------- scratch (device globals; no allocation allowed) ----------
__device__ float     g_agg[NN * D];     // h_neigh (already mean-divided)
__device__ float     g_h[NN * D];       // layer-0 output (post-relu)
__device__ int       g_deg[NN];
__device__ int       g_rowStart[NN];
__device__ int       g_cursor[NN];
__device__ int       g_csr[NE];         // src ids grouped by dst
__device__ int       g_blockSum[NB_SCAN];
__device__ int       g_blockOff[NB_SCAN];
__device__ unsigned  g_fEnc[NG * D];    // order-preserving encoded max

// order-preserving float <-> uint encoding for atomicMax
__device__ __forceinline__ unsigned encf(float f) {
    unsigned u = __float_as_uint(f);
    return (u & 0x80000000u) ? ~u : (u | 0x80000000u);
}
__device__ __forceinline__ float decf(unsigned u) {
    return __uint_as_float((u & 0x80000000u) ? (u ^ 0x80000000u) : ~u);
}

// ---------------- CSR build -------------------------------------------------
__global__ void k_init() {
    int i = blockIdx.x * blockDim.x + threadIdx.x;
    if (i < NN) { g_deg[i] = 0; g_cursor[i] = 0; }
    if (i < NG * D) g_fEnc[i] = 0u;
}

__global__ void k_hist(const int* __restrict__ dst) {
    int e = blockIdx.x * blockDim.x + threadIdx.x;
    if (e < NE) atomicAdd(&g_deg[dst[e]], 1);
}

__global__ void k_scan1() {
    __shared__ int s[SCAN_B];
    int t = threadIdx.x;
    int i = blockIdx.x * SCAN_B + t;
    int v = (i < NN) ? g_deg[i] : 0;
    s[t] = v;
    __syncthreads();
    for (int off = 1; off < SCAN_B; off <<= 1) {
        int a = (t >= off) ? s[t - off] : 0;
        __syncthreads();
        s[t] += a;
        __syncthreads();
    }
    if (i < NN) g_rowStart[i] = s[t] - v;          // exclusive within block
    if (t == SCAN_B - 1) g_blockSum[blockIdx.x] = s[t];
}

__global__ void k_scan2() {
    if (threadIdx.x == 0) {
        int run = 0;
        for (int j = 0; j < NB_SCAN; j++) {
            int v = g_blockSum[j];
            g_blockOff[j] = run;
            run += v;
        }
    }
}

__global__ void k_scan3() {
    int i = blockIdx.x * blockDim.x + threadIdx.x;
    if (i < NN) g_rowStart[i] += g_blockOff[i >> 10];
}

__global__ void k_fill(const int* __restrict__ src, const int* __restrict__ dst) {
    int e = blockIdx.x * blockDim.x + threadIdx.x;
    if (e < NE) {
        int d = dst[e];
        int p = atomicAdd(&g_cursor[d], 1);
        g_csr[g_rowStart[d] + p] = src[e];
    }
}

// ---------------- mean aggregation (gather, atomic-free) --------------------
// 16 threads per node, one float4 column-chunk each. L1==false reads external
// x; L1==true reads g_h. Writes mean directly into g_agg.
template <bool L1>
__global__ void k_agg(const float4* __restrict__ xp4) {
    int tid = blockIdx.x * blockDim.x + threadIdx.x;
    int n = tid >> 4;
    if (n >= NN) return;
    int c = tid & 15;
    const float4* X4 = L1 ? (const float4*)g_h : xp4;

    int start = g_rowStart[n];
    int d = g_deg[n];
    const int* __restrict__ lst = g_csr + start;

    float4 acc = make_float4(0.f, 0.f, 0.f, 0.f);
    int j = 0;
    for (; j + 4 <= d; j += 4) {
        int s0 = lst[j], s1 = lst[j + 1], s2 = lst[j + 2], s3 = lst[j + 3];
        float4 v0 = X4[s0 * 16 + c];
        float4 v1 = X4[s1 * 16 + c];
        float4 v2 = X4[s2 * 16 + c];
        float4 v3 = X4[s3 * 16 + c];
        acc.x += (v0.x + v1.x) + (v2.x + v3.x);
        acc.y += (v0.y + v1.y) + (v2.y + v3.y);
        acc.z += (v0.z + v1.z) + (v2.z + v3.z);
        acc.w += (v0.w + v1.w) + (v2.w + v3.w);
    }
    for (; j < d; j++) {
        float4 v = X4[lst[j] * 16 + c];
        acc.x += v.x; acc.y += v.y; acc.z += v.z; acc.w += v.w;
    }
    float rd = 1.0f / fmaxf((float)d, 1.0f);
    float4 r = make_float4(acc.x * rd, acc.y * rd, acc.z * rd, acc.w * rd);
    ((float4*)g_agg)[n * 16 + c] = r;
}

// ---------------- fused dual-GEMM per 32-node tile --------------------------
// out[n][c] = sum_k X[n][k]*Wself[k][c] + HN[n][k]*Wneigh[k][c]
// 256 threads: colpair cp = t&31 (cols 2cp,2cp+1), node group nb = (t>>5)*4.
template <bool RELU, bool MAXPOOL, bool L1>
__global__ __launch_bounds__(256) void k_node(
    const float* __restrict__ Xp,
    const float* __restrict__ Wself,
    const float* __restrict__ Wneigh,
    float* __restrict__ OUTp,
    const int* __restrict__ gids)
{
    __shared__ float sWs[D * D];
    __shared__ float sWn[D * D];
    __shared__ float sx[32 * D];
    __shared__ float shn[32 * D];

    const float* X = L1 ? (const float*)g_h : Xp;
    float* OUT = L1 ? OUTp : (float*)g_h;

    int t = threadIdx.x;
    int base = blockIdx.x * 32;

    {   // stage W tiles + 32 node rows (all contiguous float4 copies)
        float4* d1 = (float4*)sWs;  const float4* s1 = (const float4*)Wself;
        float4* d2 = (float4*)sWn;  const float4* s2 = (const float4*)Wneigh;
        #pragma unroll
        for (int i = t; i < D * D / 4; i += 256) { d1[i] = s1[i]; d2[i] = s2[i]; }
        float4* d3 = (float4*)sx;   const float4* s3 = (const float4*)(X + base * D);
        float4* d4 = (float4*)shn;  const float4* s4 = (const float4*)(g_agg + base * D);
        #pragma unroll
        for (int i = t; i < 32 * D / 4; i += 256) { d3[i] = s3[i]; d4[i] = s4[i]; }
    }
    __syncthreads();

    int cp = t & 31;
    int nb = (t >> 5) * 4;

    float2 a0 = {0.f, 0.f}, a1 = {0.f, 0.f}, a2 = {0.f, 0.f}, a3 = {0.f, 0.f};
    const float2* Ws2 = (const float2*)sWs;
    const float2* Wn2 = (const float2*)sWn;

    #pragma unroll 8
    for (int k = 0; k < D; k++) {
        float2 ws = Ws2[k * 32 + cp];
        float2 wn = Wn2[k * 32 + cp];
        float x0 = sx[(nb + 0) * D + k];
        float x1 = sx[(nb + 1) * D + k];
        float x2 = sx[(nb + 2) * D + k];
        float x3 = sx[(nb + 3) * D + k];
        float h0 = shn[(nb + 0) * D + k];
        float h1 = shn[(nb + 1) * D + k];
        float h2 = shn[(nb + 2) * D + k];
        float h3 = shn[(nb + 3) * D + k];
        a0.x = fmaf(x0, ws.x, fmaf(h0, wn.x, a0.x));
        a0.y = fmaf(x0, ws.y, fmaf(h0, wn.y, a0.y));
        a1.x = fmaf(x1, ws.x, fmaf(h1, wn.x, a1.x));
        a1.y = fmaf(x1, ws.y, fmaf(h1, wn.y, a1.y));
        a2.x = fmaf(x2, ws.x, fmaf(h2, wn.x, a2.x));
        a2.y = fmaf(x2, ws.y, fmaf(h2, wn.y, a2.y));
        a3.x = fmaf(x3, ws.x, fmaf(h3, wn.x, a3.x));
        a3.y = fmaf(x3, ws.y, fmaf(h3, wn.y, a3.y));
    }

    if (RELU) {
        a0.x = fmaxf(a0.x, 0.f); a0.y = fmaxf(a0.y, 0.f);
        a1.x = fmaxf(a1.x, 0.f); a1.y = fmaxf(a1.y, 0.f);
        a2.x = fmaxf(a2.x, 0.f); a2.y = fmaxf(a2.y, 0.f);
        a3.x = fmaxf(a3.x, 0.f); a3.y = fmaxf(a3.y, 0.f);
    }

    float2* O2 = (float2*)OUT;
    O2[(base + nb + 0) * 32 + cp] = a0;
    O2[(base + nb + 1) * 32 + cp] = a1;
    O2[(base + nb + 2) * 32 + cp] = a2;
    O2[(base + nb + 3) * 32 + cp] = a3;

    if (MAXPOOL) {
        int g0  = gids[base];
        int g31 = gids[base + 31];
        __syncthreads();                 // done reading sWs; reuse as scratch
        unsigned* bmax = (unsigned*)sWs;
        if (t < D) bmax[t] = 0u;
        __syncthreads();
        if (g0 == g31) {                 // graph_ids sorted -> uniform block
            unsigned e0 = encf(fmaxf(fmaxf(a0.x, a1.x), fmaxf(a2.x, a3.x)));
            unsigned e1 = encf(fmaxf(fmaxf(a0.y, a1.y), fmaxf(a2.y, a3.y)));
            atomicMax(&bmax[2 * cp], e0);
            atomicMax(&bmax[2 * cp + 1], e1);
            __syncthreads();
            if (t < D) atomicMax(&g_fEnc[g0 * D + t], bmax[t]);
        } else {                         // rare boundary block: per-node
            int ga = gids[base + nb + 0];
            int gb = gids[base + nb + 1];
            int gc = gids[base + nb + 2];
            int gd = gids[base + nb + 3];
            atomicMax(&g_fEnc[ga * D + 2 * cp],     encf(a0.x));
            atomicMax(&g_fEnc[ga * D + 2 * cp + 1], encf(a0.y));
            atomicMax(&g_fEnc[gb * D + 2 * cp],     encf(a1.x));
            atomicMax(&g_fEnc[gb * D + 2 * cp + 1], encf(a1.y));
            atomicMax(&g_fEnc[gc * D + 2 * cp],     encf(a2.x));
            atomicMax(&g_fEnc[gc * D + 2 * cp + 1], encf(a2.y));
            atomicMax(&g_fEnc[gd * D + 2 * cp],     encf(a3.x));
            atomicMax(&g_fEnc[gd * D + 2 * cp + 1], encf(a3.y));
        }
    }
}

__global__ void k_decode(float* __restrict__ out) {
    int i = blockIdx.x * blockDim.x + threadIdx.x;
    if (i < NG * D) out[i] = decf(g_fEnc[i]);
}

// ---------------- launch ----------------------------------------------------
extern "C" void kernel_launch(void* const* d_in, const int* in_sizes, int n_in,
                              void* d_out, int out_size) {
    const float* x   = (const float*)d_in[0];
    const int*   src = (const int*)d_in[1];
    const int*   dst = (const int*)d_in[2];
    const int*   gid = (const int*)d_in[3];
    const float* W0s = (const float*)d_in[4];
    const float* W0n = (const float*)d_in[5];
    const float* W1s = (const float*)d_in[6];
    const float* W1n = (const float*)d_in[7];
    float* out  = (float*)d_out;
    float* outF = out;              // [64, 64]
    float* outE = out + NG * D;     // [100000, 64]

    // CSR build (per replay; all graph-capturable)
    k_init <<<(NN + 255) / 256, 256>>>();
    k_hist <<<(NE + 255) / 256, 256>>>(dst);
    k_scan1<<<NB_SCAN, SCAN_B>>>();
    k_scan2<<<1, 32>>>();
    k_scan3<<<(NN + 255) / 256, 256>>>();
    k_fill <<<(NE + 255) / 256, 256>>>(src, dst);

    // layer 0
    k_agg<false><<<(NN * 16 + 255) / 256, 256>>>((const float4*)x);
    k_node<true, false, false><<<NN / 32, 256>>>(x, W0s, W0n, nullptr, gid);

    // layer 1
    k_agg<true><<<(NN * 16 + 255) / 256, 256>>>(nullptr);
    k_node<false, true, true><<<NN / 32, 256>>>(nullptr, W1s, W1n, outE, gid);

    // readout decode
    k_decode<<<(NG * D + 255) / 256, 256>>>(outF);
}

// round 7
// speedup vs baseline: 1.4044x; 1.4044x over previous
#include <cuda_runtime.h>
#include <cuda_fp16.h>
#include <cstdint>

#define NN 100000
#define NE 1600000
#define NG 64
#define D  64
#define SCAN_B 1024
#define NB_SCAN ((NN + SCAN_B - 1) / SCAN_B)   // 98
#define MT 128                                  // gemm tile rows
#define NBLK_G ((NN + MT - 1) / MT)             // 782

// ---------------- scratch (device globals; no allocation allowed) ----------
__device__ float    g_S[NN * D];      // self-term  X@Wself (fp32)
__device__ float    g_h[NN * D];      // layer-0 output (post-relu)
__device__ __half   g_P[NN * D];      // neighbor-term X@Wneigh (fp16)
__device__ __half   g_Bh[2 * 128 * 64];  // split weights hi, [layer][n][k]
__device__ __half   g_Bl[2 * 128 * 64];  // split weights lo
__device__ int      g_deg[NN];
__device__ int      g_rowStart[NN];
__device__ int      g_cursor[NN];
__device__ int      g_csr[NE];
__device__ int      g_blockSum[NB_SCAN];
__device__ int      g_blockOff[NB_SCAN];
__device__ unsigned g_fEnc[NG * D];

// ---------------- small helpers ---------------------------------------------
__device__ __forceinline__ unsigned encf(float f) {
    unsigned u = __float_as_uint(f);
    return (u & 0x80000000u) ? ~u : (u | 0x80000000u);
}
__device__ __forceinline__ float decf(unsigned u) {
    return __uint_as_float((u & 0x80000000u) ? (u ^ 0x80000000u) : ~u);
}
__device__ __forceinline__ uint32_t pack2(__half a, __half b) {
    __half2 h = __halves2half2(a, b);
    return *reinterpret_cast<uint32_t*>(&h);
}

// m16n8k16 fp16 HMMA, fp32 accumulate in-place (portable PTX, no sm_103a gate)
__device__ __forceinline__ void mma16816(float* d, const uint32_t* a, const uint32_t* b) {
    asm volatile(
        "mma.sync.aligned.m16n8k16.row.col.f32.f16.f16.f32 "
        "{%0,%1,%2,%3}, {%4,%5,%6,%7}, {%8,%9}, {%0,%1,%2,%3};"
        : "+f"(d[0]), "+f"(d[1]), "+f"(d[2]), "+f"(d[3])
        : "r"(a[0]), "r"(a[1]), "r"(a[2]), "r"(a[3]), "r"(b[0]), "r"(b[1]));
}

// ---------------- CSR build -------------------------------------------------
__global__ void k_init() {
    int i = blockIdx.x * blockDim.x + threadIdx.x;
    if (i < NN) { g_deg[i] = 0; g_cursor[i] = 0; }
    if (i < NG * D) g_fEnc[i] = 0u;
}

__global__ void k_hist(const int* __restrict__ dst) {
    int e = blockIdx.x * blockDim.x + threadIdx.x;
    if (e < NE) atomicAdd(&g_deg[dst[e]], 1);
}

__global__ void k_scan1() {
    __shared__ int s[SCAN_B];
    int t = threadIdx.x;
    int i = blockIdx.x * SCAN_B + t;
    int v = (i < NN) ? g_deg[i] : 0;
    s[t] = v;
    __syncthreads();
    for (int off = 1; off < SCAN_B; off <<= 1) {
        int a = (t >= off) ? s[t - off] : 0;
        __syncthreads();
        s[t] += a;
        __syncthreads();
    }
    if (i < NN) g_rowStart[i] = s[t] - v;
    if (t == SCAN_B - 1) g_blockSum[blockIdx.x] = s[t];
}

__global__ void k_scan2() {          // parallel scan of 98 block sums
    __shared__ int s[128];
    int t = threadIdx.x;
    int v = (t < NB_SCAN) ? g_blockSum[t] : 0;
    s[t] = v;
    __syncthreads();
    for (int off = 1; off < 128; off <<= 1) {
        int a = (t >= off) ? s[t - off] : 0;
        __syncthreads();
        s[t] += a;
        __syncthreads();
    }
    if (t < NB_SCAN) g_blockOff[t] = s[t] - v;
}

__global__ void k_scan3() {
    int i = blockIdx.x * blockDim.x + threadIdx.x;
    if (i < NN) g_rowStart[i] += g_blockOff[i >> 10];
}

__global__ void k_fill(const int* __restrict__ src, const int* __restrict__ dst) {
    int e = blockIdx.x * blockDim.x + threadIdx.x;
    if (e < NE) {
        int d = dst[e];
        int p = atomicAdd(&g_cursor[d], 1);
        g_csr[g_rowStart[d] + p] = src[e];
    }
}

// ---------------- weight split (both layers, B = [N=128 rows][K=64] fp16) ---
__global__ void k_wsplit(const float* __restrict__ W0s, const float* __restrict__ W0n,
                         const float* __restrict__ W1s, const float* __restrict__ W1n) {
    int i = blockIdx.x * blockDim.x + threadIdx.x;   // 0..16383
    if (i >= 2 * 128 * 64) return;
    int layer = i >> 13;
    int r = i & 8191;
    int n = r >> 6;
    int k = r & 63;
    const float* W = (layer == 0) ? (n < 64 ? W0s : W0n) : (n < 64 ? W1s : W1n);
    float w = W[k * 64 + (n & 63)];
    __half hi = __float2half_rn(w);
    __half lo = __float2half_rn(w - __half2float(hi));
    g_Bh[i] = hi;
    g_Bl[i] = lo;
}

// ---------------- HMMA GEMM: [S|P] = X @ [Wself|Wneigh] ---------------------
// M=128 rows/block (8 warps x 16 rows), N=128, K=64.
// 3-term split-fp16: Ah@Bh + Al@Bh + Ah@Bl  via mma.sync m16n8k16.
// smem word pitch 36 => fragment bank = (4*group + tid4) % 32, conflict-free.
#define PITCH 36
#define AH_W 0
#define AL_W (128 * PITCH)
#define BH_W (2 * 128 * PITCH)
#define BL_W (3 * 128 * PITCH)
#define GEMM_SMEM_B (4 * 128 * PITCH * 4)      // 73728 bytes

template <bool L1>
__global__ __launch_bounds__(256) void k_gemm(const float* __restrict__ Xin) {
    extern __shared__ uint32_t swm[];
    const float* X = L1 ? (const float*)g_h : Xin;
    int t = threadIdx.x;
    int w = t >> 5, lane = t & 31;
    int g = lane >> 2, tid4 = lane & 3;
    int base = blockIdx.x * MT;

    // ---- stage A: fp32 -> split fp16 (hi/lo), padded rows ----
    const float4* X4 = (const float4*)X;
    #pragma unroll
    for (int p = 0; p < 8; p++) {
        int i4 = t + p * 256;                  // float4 index in tile (0..2047)
        int row = i4 >> 4, c4 = i4 & 15;
        int node = base + row;
        float4 v = (node < NN) ? X4[node * 16 + c4] : make_float4(0.f, 0.f, 0.f, 0.f);
        __half h0 = __float2half_rn(v.x), h1 = __float2half_rn(v.y),
               h2 = __float2half_rn(v.z), h3 = __float2half_rn(v.w);
        __half l0 = __float2half_rn(v.x - __half2float(h0));
        __half l1 = __float2half_rn(v.y - __half2float(h1));
        __half l2 = __float2half_rn(v.z - __half2float(h2));
        __half l3 = __float2half_rn(v.w - __half2float(h3));
        int o = row * PITCH + c4 * 2;
        swm[AH_W + o]     = pack2(h0, h1);
        swm[AH_W + o + 1] = pack2(h2, h3);
        swm[AL_W + o]     = pack2(l0, l1);
        swm[AL_W + o + 1] = pack2(l2, l3);
    }
    // ---- stage B: prebuilt split fp16 [n][k] ----
    const uint4* Bh4 = (const uint4*)(g_Bh + (L1 ? 8192 : 0));
    const uint4* Bl4 = (const uint4*)(g_Bl + (L1 ? 8192 : 0));
    #pragma unroll
    for (int p = 0; p < 4; p++) {
        int i = t + p * 256;                   // uint4 index (0..1023)
        int n = i >> 3, q = i & 7;
        *(uint4*)&swm[BH_W + n * PITCH + q * 4] = Bh4[i];
        *(uint4*)&swm[BL_W + n * PITCH + q * 4] = Bl4[i];
    }
    __syncthreads();

    float acc[16][4];
    #pragma unroll
    for (int nt = 0; nt < 16; nt++)
        acc[nt][0] = acc[nt][1] = acc[nt][2] = acc[nt][3] = 0.f;

    int ar0 = (w * 16 + g) * PITCH;
    int ar1 = (w * 16 + g + 8) * PITCH;

    #pragma unroll
    for (int s = 0; s < 4; s++) {              // K = 4 x 16
        int kb = 8 * s;
        uint32_t ah[4], al[4];
        ah[0] = swm[AH_W + ar0 + kb + tid4];
        ah[1] = swm[AH_W + ar1 + kb + tid4];
        ah[2] = swm[AH_W + ar0 + kb + 4 + tid4];
        ah[3] = swm[AH_W + ar1 + kb + 4 + tid4];
        al[0] = swm[AL_W + ar0 + kb + tid4];
        al[1] = swm[AL_W + ar1 + kb + tid4];
        al[2] = swm[AL_W + ar0 + kb + 4 + tid4];
        al[3] = swm[AL_W + ar1 + kb + 4 + tid4];
        #pragma unroll
        for (int nt = 0; nt < 16; nt++) {
            int br = (nt * 8 + g) * PITCH + kb;
            uint32_t bh[2], bl[2];
            bh[0] = swm[BH_W + br + tid4];
            bh[1] = swm[BH_W + br + 4 + tid4];
            bl[0] = swm[BL_W + br + tid4];
            bl[1] = swm[BL_W + br + 4 + tid4];
            mma16816(acc[nt], ah, bh);
            mma16816(acc[nt], al, bh);
            mma16816(acc[nt], ah, bl);
        }
    }

    // ---- epilogue: cols 0..63 -> g_S (fp32), cols 64..127 -> g_P (fp16) ----
    int node0 = base + w * 16 + g;
    int node1 = node0 + 8;
    #pragma unroll
    for (int nt = 0; nt < 8; nt++) {
        int col = nt * 8 + tid4 * 2;
        if (node0 < NN) *(float2*)&g_S[node0 * 64 + col] = make_float2(acc[nt][0], acc[nt][1]);
        if (node1 < NN) *(float2*)&g_S[node1 * 64 + col] = make_float2(acc[nt][2], acc[nt][3]);
    }
    #pragma unroll
    for (int nt = 8; nt < 16; nt++) {
        int col = (nt - 8) * 8 + tid4 * 2;
        if (node0 < NN)
            *(uint32_t*)&g_P[node0 * 64 + col] = pack2(__float2half_rn(acc[nt][0]),
                                                       __float2half_rn(acc[nt][1]));
        if (node1 < NN)
            *(uint32_t*)&g_P[node1 * 64 + col] = pack2(__float2half_rn(acc[nt][2]),
                                                       __float2half_rn(acc[nt][3]));
    }
}

// ---------------- fused aggregation + epilogue ------------------------------
// out[n] = S[n] + mean_{u in N(n)} P[u];  layer0: relu -> g_h; layer1: -> E + maxpool
template <bool FINAL>
__global__ __launch_bounds__(256) void k_aggfuse(float* __restrict__ E,
                                                 const int* __restrict__ gids) {
    int t = threadIdx.x;
    int base = blockIdx.x * 32;
    int n = base + (t >> 3);
    int c = t & 7;                                   // cols 8c..8c+7

    int start = g_rowStart[n];
    int deg = g_deg[n];
    const int* __restrict__ lst = g_csr + start;
    const uint4* __restrict__ P4 = (const uint4*)g_P;

    float2 a0 = {0.f, 0.f}, a1 = {0.f, 0.f}, a2 = {0.f, 0.f}, a3 = {0.f, 0.f};
    int j = 0;
    for (; j + 2 <= deg; j += 2) {
        int s0 = lst[j], s1 = lst[j + 1];
        uint4 v0 = P4[s0 * 8 + c];
        uint4 v1 = P4[s1 * 8 + c];
        float2 f;
        f = __half22float2(*(__half2*)&v0.x); a0.x += f.x; a0.y += f.y;
        f = __half22float2(*(__half2*)&v0.y); a1.x += f.x; a1.y += f.y;
        f = __half22float2(*(__half2*)&v0.z); a2.x += f.x; a2.y += f.y;
        f = __half22float2(*(__half2*)&v0.w); a3.x += f.x; a3.y += f.y;
        f = __half22float2(*(__half2*)&v1.x); a0.x += f.x; a0.y += f.y;
        f = __half22float2(*(__half2*)&v1.y); a1.x += f.x; a1.y += f.y;
        f = __half22float2(*(__half2*)&v1.z); a2.x += f.x; a2.y += f.y;
        f = __half22float2(*(__half2*)&v1.w); a3.x += f.x; a3.y += f.y;
    }
    for (; j < deg; j++) {
        uint4 v0 = P4[lst[j] * 8 + c];
        float2 f;
        f = __half22float2(*(__half2*)&v0.x); a0.x += f.x; a0.y += f.y;
        f = __half22float2(*(__half2*)&v0.y); a1.x += f.x; a1.y += f.y;
        f = __half22float2(*(__half2*)&v0.z); a2.x += f.x; a2.y += f.y;
        f = __half22float2(*(__half2*)&v0.w); a3.x += f.x; a3.y += f.y;
    }

    float rd = 1.0f / fmaxf((float)deg, 1.0f);
    const float4* S4 = (const float4*)g_S;
    float4 sA = S4[n * 16 + c * 2];
    float4 sB = S4[n * 16 + c * 2 + 1];

    float o0 = sA.x + a0.x * rd, o1 = sA.y + a0.y * rd;
    float o2 = sA.z + a1.x * rd, o3 = sA.w + a1.y * rd;
    float o4 = sB.x + a2.x * rd, o5 = sB.y + a2.y * rd;
    float o6 = sB.z + a3.x * rd, o7 = sB.w + a3.y * rd;

    if (!FINAL) {
        float4* H4 = (float4*)g_h;
        H4[n * 16 + c * 2]     = make_float4(fmaxf(o0, 0.f), fmaxf(o1, 0.f),
                                             fmaxf(o2, 0.f), fmaxf(o3, 0.f));
        H4[n * 16 + c * 2 + 1] = make_float4(fmaxf(o4, 0.f), fmaxf(o5, 0.f),
                                             fmaxf(o6, 0.f), fmaxf(o7, 0.f));
    } else {
        float4* E4 = (float4*)E;
        E4[n * 16 + c * 2]     = make_float4(o0, o1, o2, o3);
        E4[n * 16 + c * 2 + 1] = make_float4(o4, o5, o6, o7);

        __shared__ unsigned bmax[64];
        if (t < 64) bmax[t] = 0u;
        int g0 = gids[base], g31 = gids[base + 31];
        __syncthreads();
        float m[8] = {o0, o1, o2, o3, o4, o5, o6, o7};
        if (g0 == g31) {                       // whole block = one graph (sorted ids)
            #pragma unroll
            for (int q = 0; q < 8; q++) {
                m[q] = fmaxf(m[q], __shfl_xor_sync(0xffffffffu, m[q], 8));
                m[q] = fmaxf(m[q], __shfl_xor_sync(0xffffffffu, m[q], 16));
            }
            if ((t & 31) < 8) {
                #pragma unroll
                for (int q = 0; q < 8; q++) atomicMax(&bmax[c * 8 + q], encf(m[q]));
            }
            __syncthreads();
            if (t < 64) atomicMax(&g_fEnc[g0 * 64 + t], bmax[t]);
        } else {                               // rare boundary block
            int gn = gids[n];
            #pragma unroll
            for (int q = 0; q < 8; q++) atomicMax(&g_fEnc[gn * 64 + c * 8 + q], encf(m[q]));
        }
    }
}

__global__ void k_decode(float* __restrict__ out) {
    int i = blockIdx.x * blockDim.x + threadIdx.x;
    if (i < NG * D) out[i] = decf(g_fEnc[i]);
}

// ---------------- launch ----------------------------------------------------
extern "C" void kernel_launch(void* const* d_in, const int* in_sizes, int n_in,
                              void* d_out, int out_size) {
    const float* x   = (const float*)d_in[0];
    const int*   src = (const int*)d_in[1];
    const int*   dst = (const int*)d_in[2];
    const int*   gid = (const int*)d_in[3];
    const float* W0s = (const float*)d_in[4];
    const float* W0n = (const float*)d_in[5];
    const float* W1s = (const float*)d_in[6];
    const float* W1n = (const float*)d_in[7];
    float* outF = (float*)d_out;               // [64, 64]
    float* outE = (float*)d_out + NG * D;      // [100000, 64]

    cudaFuncSetAttribute(k_gemm<false>, cudaFuncAttributeMaxDynamicSharedMemorySize, GEMM_SMEM_B);
    cudaFuncSetAttribute(k_gemm<true>,  cudaFuncAttributeMaxDynamicSharedMemorySize, GEMM_SMEM_B);

    // weight split + CSR build
    k_wsplit<<<64, 256>>>(W0s, W0n, W1s, W1n);
    k_init  <<<(NN + 255) / 256, 256>>>();
    k_hist  <<<(NE + 255) / 256, 256>>>(dst);
    k_scan1 <<<NB_SCAN, SCAN_B>>>();
    k_scan2 <<<1, 128>>>();
    k_scan3 <<<(NN + 255) / 256, 256>>>();
    k_fill  <<<(NE + 255) / 256, 256>>>(src, dst);

    // layer 0: [S|P] = x @ [W0s|W0n], then h = relu(S + mean-agg(P))
    k_gemm<false><<<NBLK_G, 256, GEMM_SMEM_B>>>(x);
    k_aggfuse<false><<<NN / 32, 256>>>(nullptr, gid);

    // layer 1: [S|P] = h @ [W1s|W1n], then e = S + mean-agg(P), maxpool
    k_gemm<true><<<NBLK_G, 256, GEMM_SMEM_B>>>(nullptr);
    k_aggfuse<true><<<NN / 32, 256>>>(outE, gid);

    k_decode<<<(NG * D + 255) / 256, 256>>>(outF);
}